// round 12
// baseline (speedup 1.0000x reference)
#include <cuda_runtime.h>
#include <math.h>

#define Bb 64
#define Nn 1024
#define Hh 64
#define Tt 10

// ---------------- scratch (device globals; permuted row space) -----------------
__device__ __align__(16) float g_nrmP[Bb*Nn*Hh];   // emb/||emb||, bucket order
__device__ __align__(16) float g_xw0 [Bb*Nn*Hh];   // emb @ W0^T, bucket order
__device__ __align__(16) float g_xw1 [Bb*Nn*Hh];   // h1  @ W1^T, bucket order
__device__ __align__(16) float g_h2P [Bb*Nn*Hh];
__device__ __align__(16) float g_G   [Bb*Tt*Hh*Hh];
__device__ int g_pos[Bb*Nn];
__device__ int g_off[Bb*Tt];
__device__ int g_cnt[Bb*Tt];
__device__ __align__(16) float g_ctx[Bb*Hh];

typedef unsigned long long ull;

#define FMA4(A, s, v) { (A).x += (s)*(v).x; (A).y += (s)*(v).y; (A).z += (s)*(v).z; (A).w += (s)*(v).w; }
#define FMA2(acc, a2, b2)  asm("fma.rn.f32x2 %0, %1, %2, %0;" : "+l"(acc) : "l"(a2), "l"(b2))
#define PACK_DUP(out, x)   asm("mov.b64 %0, {%1, %1};" : "=l"(out) : "r"(__float_as_uint(x)))
#define UNPACK2(lo, hi, p) asm("mov.b64 {%0, %1}, %2;" : "=r"(lo), "=r"(hi) : "l"(p))

__device__ __forceinline__ float4 acc_f4(ull p0, ull p1) {
    unsigned a, b, c, d;
    UNPACK2(a, b, p0); UNPACK2(c, d, p1);
    return make_float4(__uint_as_float(a), __uint_as_float(b),
                       __uint_as_float(c), __uint_as_float(d));
}
// 16 fp32 FMAs as 8 packed FFMA2
__device__ __forceinline__ void mk16(ull* acc, float a0, float a1, float a2, float a3,
                                     const float* bp) {
    ulonglong2 bv = *(const ulonglong2*)bp;
    ull ap;
    PACK_DUP(ap, a0); FMA2(acc[0], ap, bv.x); FMA2(acc[1], ap, bv.y);
    PACK_DUP(ap, a1); FMA2(acc[2], ap, bv.x); FMA2(acc[3], ap, bv.y);
    PACK_DUP(ap, a2); FMA2(acc[4], ap, bv.x); FMA2(acc[5], ap, bv.y);
    PACK_DUP(ap, a3); FMA2(acc[6], ap, bv.x); FMA2(acc[7], ap, bv.y);
}

// ---------------- K0: bucket ----------------------------------------------------
__global__ __launch_bounds__(1024) void k_bucket(const int* __restrict__ types)
{
    __shared__ int s_cnt[16];
    __shared__ int s_off[16];
    int b = blockIdx.x, n = threadIdx.x;
    if (n < Tt) s_cnt[n] = 0;
    if (n < 64) g_ctx[b*64 + n] = 0.f;
    __syncthreads();
    int t = types[b*Nn + n];
    int rank = atomicAdd(&s_cnt[t], 1);
    __syncthreads();
    if (n == 0) {
        int a = 0;
        #pragma unroll
        for (int i = 0; i < Tt; ++i) { s_off[i] = a; a += s_cnt[i]; }
    }
    __syncthreads();
    g_pos[b*Nn + n] = b*Nn + s_off[t] + rank;
    if (n < Tt) { g_cnt[b*Tt + n] = s_cnt[n]; g_off[b*Tt + n] = s_off[n]; }
}

// ---------------- K1: encoder -> nrmP + HW0 = emb @ W0^T (permuted) -------------
__global__ __launch_bounds__(256) void k_enc(
    const float* __restrict__ tf,
    const float* __restrict__ w1, const float* __restrict__ b1,
    const float* __restrict__ w2, const float* __restrict__ b2,
    const float* __restrict__ gw)
{
    __shared__ __align__(16) float s_A[64*68];   // h1, then emb tile
    __shared__ __align__(16) float s_B[64*68];   // w2^T, then W0^T
    __shared__ __align__(16) float s_f[192];
    __shared__ __align__(16) float s_w1[192];
    __shared__ __align__(16) float s_b1[64];
    __shared__ __align__(16) float s_b2[64];
    int tid = threadIdx.x;
    int tx = tid & 15, ty = tid >> 4;
    int base = blockIdx.x * 64;

    #pragma unroll
    for (int it = 0; it < 16; ++it) {
        int e = tid + it*256;
        int j = e >> 6, k = e & 63;
        s_B[k*68 + j] = w2[e];                 // w2^T
    }
    if (tid < 192) { s_f[tid] = tf[base*3 + tid]; s_w1[tid] = w1[tid]; }
    if (tid < 64)  { s_b1[tid] = b1[tid]; s_b2[tid] = b2[tid]; }
    __syncthreads();

    #pragma unroll
    for (int it = 0; it < 16; ++it) {
        int e = tid + it*256;
        int row = e >> 6, k = e & 63;
        float h = s_f[row*3+0]*s_w1[k*3+0] + s_f[row*3+1]*s_w1[k*3+1]
                + s_f[row*3+2]*s_w1[k*3+2] + s_b1[k];
        s_A[row*68 + k] = fmaxf(h, 0.f);
    }
    __syncthreads();

    // emb = h1 @ w2^T + b2
    float4 acc[4];
    #pragma unroll
    for (int i = 0; i < 4; ++i) acc[i] = make_float4(0.f,0.f,0.f,0.f);
    #pragma unroll 8
    for (int kk = 0; kk < 64; ++kk) {
        float4 bb = *(const float4*)&s_B[kk*68 + tx*4];
        float a0 = s_A[(ty*4+0)*68 + kk];
        float a1 = s_A[(ty*4+1)*68 + kk];
        float a2 = s_A[(ty*4+2)*68 + kk];
        float a3 = s_A[(ty*4+3)*68 + kk];
        FMA4(acc[0], a0, bb); FMA4(acc[1], a1, bb);
        FMA4(acc[2], a2, bb); FMA4(acc[3], a3, bb);
    }
    float4 bias = *(const float4*)&s_b2[tx*4];
    int p[4];
    #pragma unroll
    for (int i = 0; i < 4; ++i) {
        acc[i].x += bias.x; acc[i].y += bias.y;
        acc[i].z += bias.z; acc[i].w += bias.w;
        float sq = acc[i].x*acc[i].x + acc[i].y*acc[i].y
                 + acc[i].z*acc[i].z + acc[i].w*acc[i].w;
        #pragma unroll
        for (int o = 8; o > 0; o >>= 1) sq += __shfl_xor_sync(0xffffffffu, sq, o);
        float inv = 1.f / fmaxf(sqrtf(sq), 1e-12f);
        p[i] = g_pos[base + ty*4 + i];
        float4 nv = make_float4(acc[i].x*inv, acc[i].y*inv, acc[i].z*inv, acc[i].w*inv);
        *(float4*)&g_nrmP[p[i]*64 + tx*4] = nv;
    }
    __syncthreads();

    // restage: s_A = emb tile, s_B = W0^T
    #pragma unroll
    for (int i = 0; i < 4; ++i)
        *(float4*)&s_A[(ty*4+i)*68 + tx*4] = acc[i];
    #pragma unroll
    for (int it = 0; it < 16; ++it) {
        int e = tid + it*256;
        int c = e >> 6, k = e & 63;
        s_B[k*68 + c] = gw[e];                 // W0^T
    }
    __syncthreads();

    // HW0 = emb @ W0^T (no bias)
    float4 acc2[4];
    #pragma unroll
    for (int i = 0; i < 4; ++i) acc2[i] = make_float4(0.f,0.f,0.f,0.f);
    #pragma unroll 8
    for (int kk = 0; kk < 64; ++kk) {
        float4 bb = *(const float4*)&s_B[kk*68 + tx*4];
        float a0 = s_A[(ty*4+0)*68 + kk];
        float a1 = s_A[(ty*4+1)*68 + kk];
        float a2 = s_A[(ty*4+2)*68 + kk];
        float a3 = s_A[(ty*4+3)*68 + kk];
        FMA4(acc2[0], a0, bb); FMA4(acc2[1], a1, bb);
        FMA4(acc2[2], a2, bb); FMA4(acc2[3], a3, bb);
    }
    #pragma unroll
    for (int i = 0; i < 4; ++i)
        *(float4*)&g_xw0[p[i]*64 + tx*4] = acc2[i];
}

// ---------------- K2: fused gmat + combine + layer, 10-CTA cluster per batch ----
// grid (10,64), cluster (10,1,1), 256 thr
// smem floats: S0 nrm tile 4352 | S1 hw/h1 tile 4352 | S2 M' 4096 | S3 W1^T 4096 (l0)
__global__ __launch_bounds__(256) void k_fused(
    int l, const float* __restrict__ cont,
    const float* __restrict__ gw, const float* __restrict__ gb)
{
    extern __shared__ __align__(16) float sm[];
    float* S0 = sm;
    float* S1 = sm + 4352;
    float* S2 = sm + 8704;
    float* S3 = sm + 12800;
    __shared__ float s_sg[16];
    __shared__ __align__(16) float s_bias[64];
    __shared__ __align__(16) float s_csum[16][64];

    const float4* nrm4 = (const float4*)g_nrmP;
    const float*  hwf  = (l == 0) ? g_xw0 : g_xw1;
    const float4* hw4  = (const float4*)hwf;

    int t = blockIdx.x, b = blockIdx.y;
    int tid = threadIdx.x;
    int tx = tid & 15, ty = tid >> 4;

    if (tid < Tt) s_sg[tid] = 1.f / (1.f + expf(-cont[t*Tt + tid]));
    if (tid < 64) s_bias[tid] = gb[l*64 + tid];
    if (l == 0) {
        #pragma unroll
        for (int it = 0; it < 16; ++it) {
            int e = tid + it*256;
            S3[(e & 63)*64 + (e >> 6)] = gw[4096 + e];   // W1^T [k][c]
        }
    }
    int Kt = g_cnt[b*Tt + t];
    int rbase = (b << 10) + g_off[b*Tt + t];

    // ---- phase A: G' = nrm^T @ hw ----
    float4 acc[4];
    #pragma unroll
    for (int i = 0; i < 4; ++i) acc[i] = make_float4(0.f,0.f,0.f,0.f);
    for (int r0 = 0; r0 < Kt; r0 += 64) {
        __syncthreads();
        #pragma unroll
        for (int it = 0; it < 4; ++it) {
            int e = tid + it*256;
            int rr = e >> 4, kq = e & 15;
            int r = r0 + rr;
            float4 a = make_float4(0.f,0.f,0.f,0.f);
            float4 w = make_float4(0.f,0.f,0.f,0.f);
            if (r < Kt) {
                int gi = (rbase + r)*16 + kq;
                a = nrm4[gi];
                w = hw4[gi];
            }
            *(float4*)&S0[rr*68 + kq*4] = a;
            *(float4*)&S1[rr*68 + kq*4] = w;
        }
        __syncthreads();
        #pragma unroll 8
        for (int rr = 0; rr < 64; ++rr) {
            float4 a  = *(const float4*)&S0[rr*68 + ty*4];
            float4 bb = *(const float4*)&S1[rr*68 + tx*4];
            FMA4(acc[0], a.x, bb); FMA4(acc[1], a.y, bb);
            FMA4(acc[2], a.z, bb); FMA4(acc[3], a.w, bb);
        }
    }
    float* Gp = &g_G[(b*Tt + t)*4096];
    #pragma unroll
    for (int i = 0; i < 4; ++i)
        *(float4*)&Gp[(ty*4 + i)*64 + tx*4] = acc[i];

    // cluster-wide: all 10 G'[b,*] visible
    __threadfence();
    asm volatile("barrier.cluster.arrive.aligned;" ::: "memory");
    asm volatile("barrier.cluster.wait.aligned;" ::: "memory");
    __threadfence();

    if (Kt == 0) return;

    // ---- phase B: M' = sum_tp sigmoid(C[t,tp]) G'[b,tp] into S2 ----
    __syncthreads();
    const float4* Gb = (const float4*)&g_G[(size_t)b*Tt*4096];
    #pragma unroll
    for (int it = 0; it < 4; ++it) {
        int e = tid + it*256;
        float4 m = make_float4(0.f,0.f,0.f,0.f);
        #pragma unroll
        for (int tp = 0; tp < Tt; ++tp) {
            float s = s_sg[tp];
            FMA4(m, s, Gb[tp*1024 + e]);
        }
        *(float4*)&S2[(e >> 4)*64 + (e & 15)*4] = m;
    }

    // ---- phase C: per-tile layer ----
    float4 psum = make_float4(0.f,0.f,0.f,0.f);
    float4 bias = *(const float4*)&s_bias[tx*4];
    for (int r0 = 0; r0 < Kt; r0 += 64) {
        __syncthreads();
        #pragma unroll
        for (int it = 0; it < 4; ++it) {
            int e = tid + it*256;
            int rr = e >> 4, kq = e & 15;
            int r = r0 + rr;
            float4 v = make_float4(0.f,0.f,0.f,0.f);
            if (r < Kt) v = nrm4[(rbase + r)*16 + kq];
            *(float4*)&S0[rr*68 + kq*4] = v;
        }
        __syncthreads();

        // GEMM1: agg' = nrm @ M'
        ull a1[8] = {0,0,0,0,0,0,0,0};
        #pragma unroll 8
        for (int kk = 0; kk < 64; ++kk) {
            float a0 = S0[(ty*4+0)*68 + kk];
            float b0 = S0[(ty*4+1)*68 + kk];
            float c0 = S0[(ty*4+2)*68 + kk];
            float d0 = S0[(ty*4+3)*68 + kk];
            mk16(a1, a0, b0, c0, d0, &S2[kk*64 + tx*4]);
        }

        if (l == 0) {
            // h1 = relu(HW0 + agg' + b0) -> S1
            #pragma unroll
            for (int i = 0; i < 4; ++i) {
                int r = r0 + ty*4 + i;
                float4 x = acc_f4(a1[2*i], a1[2*i+1]);
                if (r < Kt) {
                    float4 hv = *(const float4*)&hwf[(rbase + r)*64 + tx*4];
                    x.x = fmaxf(x.x + hv.x + bias.x, 0.f);
                    x.y = fmaxf(x.y + hv.y + bias.y, 0.f);
                    x.z = fmaxf(x.z + hv.z + bias.z, 0.f);
                    x.w = fmaxf(x.w + hv.w + bias.w, 0.f);
                } else {
                    x = make_float4(0.f,0.f,0.f,0.f);
                }
                *(float4*)&S1[(ty*4+i)*68 + tx*4] = x;
            }
            __syncthreads();
            // GEMM2: HW1 = h1 @ W1^T (no bias, no relu)
            ull a2[8] = {0,0,0,0,0,0,0,0};
            #pragma unroll 8
            for (int kk = 0; kk < 64; ++kk) {
                float a0 = S1[(ty*4+0)*68 + kk];
                float b0 = S1[(ty*4+1)*68 + kk];
                float c0 = S1[(ty*4+2)*68 + kk];
                float d0 = S1[(ty*4+3)*68 + kk];
                mk16(a2, a0, b0, c0, d0, &S3[kk*64 + tx*4]);
            }
            #pragma unroll
            for (int i = 0; i < 4; ++i) {
                int r = r0 + ty*4 + i;
                if (r < Kt)
                    *(float4*)&g_xw1[(rbase + r)*64 + tx*4] = acc_f4(a2[2*i], a2[2*i+1]);
            }
        } else {
            // h2 = relu(HW1 + agg' + b1), store + ctx partials
            #pragma unroll
            for (int i = 0; i < 4; ++i) {
                int r = r0 + ty*4 + i;
                if (r < Kt) {
                    float4 x = acc_f4(a1[2*i], a1[2*i+1]);
                    float4 hv = *(const float4*)&hwf[(rbase + r)*64 + tx*4];
                    x.x = fmaxf(x.x + hv.x + bias.x, 0.f);
                    x.y = fmaxf(x.y + hv.y + bias.y, 0.f);
                    x.z = fmaxf(x.z + hv.z + bias.z, 0.f);
                    x.w = fmaxf(x.w + hv.w + bias.w, 0.f);
                    *(float4*)&g_h2P[(rbase + r)*64 + tx*4] = x;
                    psum.x += x.x; psum.y += x.y; psum.z += x.z; psum.w += x.w;
                }
            }
        }
    }

    if (l == 1) {
        __syncthreads();
        *(float4*)&s_csum[ty][tx*4] = psum;
        __syncthreads();
        if (tid < 64) {
            float s = 0.f;
            #pragma unroll
            for (int q = 0; q < 16; ++q) s += s_csum[q][tid];
            atomicAdd(&g_ctx[b*64 + tid], s);
        }
    }
}

// ---------------- K3: head (+GRU per block, K=64, gathers h2P via pos) ----------
__global__ __launch_bounds__(256) void k_head(
    const float* __restrict__ prev, const float* __restrict__ wih,
    const float* __restrict__ whh,  const float* __restrict__ bih,
    const float* __restrict__ bhh,
    const float* __restrict__ w1, const float* __restrict__ b1,
    const float* __restrict__ w2, const float* __restrict__ b2,
    float* __restrict__ out)
{
    __shared__ __align__(16) float s_X[64*68];
    __shared__ __align__(16) float s_W[64*68];
    __shared__ __align__(16) float s_g[320];
    __shared__ __align__(16) float s_hs[64];
    __shared__ __align__(16) float s_w2[64];
    __shared__ int s_pos[64];
    int tid = threadIdx.x;
    int tx = tid & 15, ty = tid >> 4;
    int u = blockIdx.x;
    int base = u << 6;
    int b = u >> 4;

    #pragma unroll
    for (int it = 0; it < 16; ++it) {
        int e = tid + it*256;
        int j = e >> 6, k = e & 63;
        s_W[k*68 + j] = w1[j*96 + k];
    }
    if (tid < 64) s_w2[tid] = w2[tid];
    if (tid < 64)       s_g[tid] = g_ctx[b*64 + tid] * (1.f/1024.f);
    else if (tid < 96)  s_g[tid] = prev[b*32 + (tid - 64)];
    else if (tid < 160) s_pos[tid - 96] = g_pos[base + (tid - 96)];
    __syncthreads();

    const float4* h24 = (const float4*)g_h2P;
    #pragma unroll
    for (int it = 0; it < 4; ++it) {
        int e = tid + it*256;
        int rr = e >> 4, kq = e & 15;
        *(float4*)&s_X[rr*68 + kq*4] = h24[s_pos[rr]*16 + kq];
    }
    if (tid < 96) {
        float gi = bih[tid], gh = bhh[tid];
        #pragma unroll 16
        for (int k = 0; k < 64; ++k) gi += s_g[k] * wih[tid*64 + k];
        #pragma unroll 16
        for (int k = 0; k < 32; ++k) gh += s_g[64 + k] * whh[tid*32 + k];
        s_g[96 + tid] = gi; s_g[192 + tid] = gh;
    }
    __syncthreads();
    if (tid < 32) {
        float r  = 1.f / (1.f + expf(-(s_g[96  + tid] + s_g[192 + tid])));
        float z  = 1.f / (1.f + expf(-(s_g[128 + tid] + s_g[224 + tid])));
        float nn = tanhf(s_g[160 + tid] + r * s_g[256 + tid]);
        float ns = (1.f - z)*nn + z*s_g[64 + tid];
        s_g[288 + tid] = ns;
        if ((u & 15) == 0) out[Bb*Nn + b*32 + tid] = ns;
    }
    __syncthreads();
    if (tid < 64) {
        float v = b1[tid];
        #pragma unroll
        for (int k = 0; k < 32; ++k) v += w1[tid*96 + 64 + k] * s_g[288 + k];
        s_hs[tid] = v;
    }
    __syncthreads();

    float4 hs = *(const float4*)&s_hs[tx*4];
    float4 acc[4] = {hs, hs, hs, hs};
    #pragma unroll 8
    for (int kk = 0; kk < 64; ++kk) {
        float4 bb = *(const float4*)&s_W[kk*68 + tx*4];
        float a0 = s_X[(ty*4+0)*68 + kk];
        float a1 = s_X[(ty*4+1)*68 + kk];
        float a2 = s_X[(ty*4+2)*68 + kk];
        float a3 = s_X[(ty*4+3)*68 + kk];
        FMA4(acc[0], a0, bb); FMA4(acc[1], a1, bb);
        FMA4(acc[2], a2, bb); FMA4(acc[3], a3, bb);
    }
    float4 w2v = *(const float4*)&s_w2[tx*4];
    float b2v = b2[0];
    #pragma unroll
    for (int i = 0; i < 4; ++i) {
        float y = fmaxf(acc[i].x, 0.f)*w2v.x + fmaxf(acc[i].y, 0.f)*w2v.y
                + fmaxf(acc[i].z, 0.f)*w2v.z + fmaxf(acc[i].w, 0.f)*w2v.w;
        #pragma unroll
        for (int o = 8; o > 0; o >>= 1) y += __shfl_xor_sync(0xffffffffu, y, o);
        if (tx == 0) out[base + ty*4 + i] = y + b2v;
    }
}

// ---------------- launch ---------------------------------------------------------
extern "C" void kernel_launch(void* const* d_in, const int* in_sizes, int n_in,
                              void* d_out, int out_size)
{
    const float* tf    = (const float*)d_in[0];
    const int*   types = (const int*)  d_in[1];
    const float* prev  = (const float*)d_in[2];
    const float* ew1   = (const float*)d_in[3];
    const float* eb1   = (const float*)d_in[4];
    const float* ew2   = (const float*)d_in[5];
    const float* eb2   = (const float*)d_in[6];
    const float* cont  = (const float*)d_in[7];
    const float* gw    = (const float*)d_in[8];
    const float* gb    = (const float*)d_in[9];
    const float* wih   = (const float*)d_in[10];
    const float* whh   = (const float*)d_in[11];
    const float* bih   = (const float*)d_in[12];
    const float* bhh   = (const float*)d_in[13];
    const float* hw1   = (const float*)d_in[14];
    const float* hb1   = (const float*)d_in[15];
    const float* hw2   = (const float*)d_in[16];
    const float* hb2   = (const float*)d_in[17];
    float* out = (float*)d_out;

    cudaFuncSetAttribute(k_fused, cudaFuncAttributeMaxDynamicSharedMemorySize, 67584);
    cudaFuncSetAttribute(k_fused, cudaFuncAttributeNonPortableClusterSizeAllowed, 1);

    k_bucket<<<Bb, 1024>>>(types);
    k_enc<<<1024, 256>>>(tf, ew1, eb1, ew2, eb2, gw);

    cudaLaunchAttribute cat;
    cat.id = cudaLaunchAttributeClusterDimension;
    cat.val.clusterDim.x = Tt; cat.val.clusterDim.y = 1; cat.val.clusterDim.z = 1;
    cudaLaunchConfig_t cfg = {};
    cfg.attrs = &cat;
    cfg.numAttrs = 1;
    cfg.stream = 0;
    cfg.blockDim = dim3(256, 1, 1);
    cfg.gridDim = dim3(Tt, Bb, 1);

    cfg.dynamicSmemBytes = 67584;   // S0,S1,S2,S3
    cudaLaunchKernelEx(&cfg, k_fused, 0, cont, gw, gb);
    cfg.dynamicSmemBytes = 51200;   // S0,S1,S2 only
    cudaLaunchKernelEx(&cfg, k_fused, 1, cont, gw, gb);

    k_head<<<1024, 256>>>(prev, wih, whh, bih, bhh, hw1, hb1, hw2, hb2, out);
}

// round 13
// speedup vs baseline: 1.0444x; 1.0444x over previous
#include <cuda_runtime.h>
#include <math.h>

#define Bb 64
#define Nn 1024
#define Hh 64
#define Tt 10

// ---------------- scratch (device globals; permuted row space) -----------------
__device__ __align__(16) float g_nrmP[Bb*Nn*Hh];   // emb/||emb||, bucket order
__device__ __align__(16) float g_xw0 [Bb*Nn*Hh];   // emb @ W0^T
__device__ __align__(16) float g_xw1 [Bb*Nn*Hh];   // h1  @ W1^T
__device__ __align__(16) float g_h2P [Bb*Nn*Hh];
__device__ __align__(16) float g_G   [Bb*Tt*Hh*Hh];
__device__ __align__(16) float g_M   [Bb*Tt*Hh*Hh];
__device__ int g_pos[Bb*Nn];
__device__ int g_off[Bb*Tt];
__device__ int g_cnt[Bb*Tt];
__device__ __align__(16) float g_ctx[Bb*Hh];

#define FMA4(A, s, v) { (A).x += (s)*(v).x; (A).y += (s)*(v).y; (A).z += (s)*(v).z; (A).w += (s)*(v).w; }
#define GDC_WAIT()   asm volatile("griddepcontrol.wait;" ::: "memory")
#define GDC_LAUNCH() asm volatile("griddepcontrol.launch_dependents;" ::: "memory")

// ---------------- K0: bucket ----------------------------------------------------
__global__ __launch_bounds__(1024) void k_bucket(const int* __restrict__ types)
{
    __shared__ int s_cnt[16];
    __shared__ int s_off[16];
    int b = blockIdx.x, n = threadIdx.x;
    if (n < Tt) s_cnt[n] = 0;
    if (n < 64) g_ctx[b*64 + n] = 0.f;
    __syncthreads();
    int t = types[b*Nn + n];
    int rank = atomicAdd(&s_cnt[t], 1);
    __syncthreads();
    if (n == 0) {
        int a = 0;
        #pragma unroll
        for (int i = 0; i < Tt; ++i) { s_off[i] = a; a += s_cnt[i]; }
    }
    __syncthreads();
    g_pos[b*Nn + n] = b*Nn + s_off[t] + rank;
    if (n < Tt) { g_cnt[b*Tt + n] = s_cnt[n]; g_off[b*Tt + n] = s_off[n]; }
    GDC_LAUNCH();
}

// ---------------- K1: encoder -> nrmP + HW0 = emb @ W0^T ------------------------
__global__ __launch_bounds__(256) void k_enc(
    const float* __restrict__ tf,
    const float* __restrict__ w1, const float* __restrict__ b1,
    const float* __restrict__ w2, const float* __restrict__ b2,
    const float* __restrict__ gw)
{
    __shared__ __align__(16) float s_A[64*68];
    __shared__ __align__(16) float s_B[64*68];
    __shared__ __align__(16) float s_f[192];
    __shared__ __align__(16) float s_w1[192];
    __shared__ __align__(16) float s_b1[64];
    __shared__ __align__(16) float s_b2[64];
    int tid = threadIdx.x;
    int tx = tid & 15, ty = tid >> 4;
    int base = blockIdx.x * 64;

    #pragma unroll
    for (int it = 0; it < 16; ++it) {
        int e = tid + it*256;
        int j = e >> 6, k = e & 63;
        s_B[k*68 + j] = w2[e];                 // w2^T
    }
    if (tid < 192) { s_f[tid] = tf[base*3 + tid]; s_w1[tid] = w1[tid]; }
    if (tid < 64)  { s_b1[tid] = b1[tid]; s_b2[tid] = b2[tid]; }
    __syncthreads();
    GDC_LAUNCH();

    #pragma unroll
    for (int it = 0; it < 16; ++it) {
        int e = tid + it*256;
        int row = e >> 6, k = e & 63;
        float h = s_f[row*3+0]*s_w1[k*3+0] + s_f[row*3+1]*s_w1[k*3+1]
                + s_f[row*3+2]*s_w1[k*3+2] + s_b1[k];
        s_A[row*68 + k] = fmaxf(h, 0.f);
    }
    __syncthreads();

    // emb = h1 @ w2^T + b2
    float4 acc[4];
    #pragma unroll
    for (int i = 0; i < 4; ++i) acc[i] = make_float4(0.f,0.f,0.f,0.f);
    #pragma unroll 8
    for (int kk = 0; kk < 64; ++kk) {
        float4 bb = *(const float4*)&s_B[kk*68 + tx*4];
        float a0 = s_A[(ty*4+0)*68 + kk];
        float a1 = s_A[(ty*4+1)*68 + kk];
        float a2 = s_A[(ty*4+2)*68 + kk];
        float a3 = s_A[(ty*4+3)*68 + kk];
        FMA4(acc[0], a0, bb); FMA4(acc[1], a1, bb);
        FMA4(acc[2], a2, bb); FMA4(acc[3], a3, bb);
    }
    float4 bias = *(const float4*)&s_b2[tx*4];
    GDC_WAIT();
    int p[4];
    #pragma unroll
    for (int i = 0; i < 4; ++i) {
        acc[i].x += bias.x; acc[i].y += bias.y;
        acc[i].z += bias.z; acc[i].w += bias.w;
        float sq = acc[i].x*acc[i].x + acc[i].y*acc[i].y
                 + acc[i].z*acc[i].z + acc[i].w*acc[i].w;
        #pragma unroll
        for (int o = 8; o > 0; o >>= 1) sq += __shfl_xor_sync(0xffffffffu, sq, o);
        float inv = 1.f / fmaxf(sqrtf(sq), 1e-12f);
        p[i] = g_pos[base + ty*4 + i];
        float4 nv = make_float4(acc[i].x*inv, acc[i].y*inv, acc[i].z*inv, acc[i].w*inv);
        *(float4*)&g_nrmP[p[i]*64 + tx*4] = nv;
    }
    __syncthreads();

    // restage: s_A = emb tile, s_B = W0^T
    #pragma unroll
    for (int i = 0; i < 4; ++i)
        *(float4*)&s_A[(ty*4+i)*68 + tx*4] = acc[i];
    #pragma unroll
    for (int it = 0; it < 16; ++it) {
        int e = tid + it*256;
        int c = e >> 6, k = e & 63;
        s_B[k*68 + c] = gw[e];                 // W0^T
    }
    __syncthreads();

    // HW0 = emb @ W0^T (no bias)
    float4 acc2[4];
    #pragma unroll
    for (int i = 0; i < 4; ++i) acc2[i] = make_float4(0.f,0.f,0.f,0.f);
    #pragma unroll 8
    for (int kk = 0; kk < 64; ++kk) {
        float4 bb = *(const float4*)&s_B[kk*68 + tx*4];
        float a0 = s_A[(ty*4+0)*68 + kk];
        float a1 = s_A[(ty*4+1)*68 + kk];
        float a2 = s_A[(ty*4+2)*68 + kk];
        float a3 = s_A[(ty*4+3)*68 + kk];
        FMA4(acc2[0], a0, bb); FMA4(acc2[1], a1, bb);
        FMA4(acc2[2], a2, bb); FMA4(acc2[3], a3, bb);
    }
    #pragma unroll
    for (int i = 0; i < 4; ++i)
        *(float4*)&g_xw0[p[i]*64 + tx*4] = acc2[i];
}

// ---------------- K2: G' = Nrm^T @ HW per (t,b), dense rows ---------------------
__global__ __launch_bounds__(256) void k_gmat(int l)
{
    const float4* nrm4 = (const float4*)g_nrmP;
    const float4* hw4  = (const float4*)((l == 0) ? g_xw0 : g_xw1);
    __shared__ __align__(16) float s_A [64*68];
    __shared__ __align__(16) float s_Bh[64*68];
    int t = blockIdx.x, b = blockIdx.y;
    int tid = threadIdx.x;
    int tx = tid & 15, ty = tid >> 4;
    GDC_WAIT(); GDC_LAUNCH();
    int Kt = g_cnt[b*Tt + t];
    int rbase = (b << 10) + g_off[b*Tt + t];
    float4 acc[4];
    #pragma unroll
    for (int i = 0; i < 4; ++i) acc[i] = make_float4(0.f,0.f,0.f,0.f);

    for (int r0 = 0; r0 < Kt; r0 += 64) {
        #pragma unroll
        for (int it = 0; it < 4; ++it) {
            int e = tid + it*256;
            int rr = e >> 4, kq = e & 15;
            int r = r0 + rr;
            float4 a = make_float4(0.f,0.f,0.f,0.f);
            float4 w = make_float4(0.f,0.f,0.f,0.f);
            if (r < Kt) {
                int gi = (rbase + r)*16 + kq;
                a = nrm4[gi];
                w = hw4[gi];
            }
            *(float4*)&s_A [rr*68 + kq*4] = a;
            *(float4*)&s_Bh[rr*68 + kq*4] = w;
        }
        __syncthreads();
        #pragma unroll 8
        for (int rr = 0; rr < 64; ++rr) {
            float4 a  = *(const float4*)&s_A [rr*68 + ty*4];
            float4 bb = *(const float4*)&s_Bh[rr*68 + tx*4];
            FMA4(acc[0], a.x, bb); FMA4(acc[1], a.y, bb);
            FMA4(acc[2], a.z, bb); FMA4(acc[3], a.w, bb);
        }
        __syncthreads();
    }
    float* Gp = &g_G[(b*Tt + t)*4096];
    #pragma unroll
    for (int i = 0; i < 4; ++i)
        *(float4*)&Gp[(ty*4 + i)*64 + tx*4] = acc[i];
}

// ---------------- K2b: M' = sum_t sigmoid(C) G' ---------------------------------
__global__ __launch_bounds__(128) void k_combine(const float* __restrict__ cont)
{
    __shared__ float s_S[Tt*Tt];
    int b = blockIdx.x, tid = threadIdx.x;
    if (tid < Tt*Tt) s_S[tid] = 1.f / (1.f + expf(-cont[tid]));
    __syncthreads();
    GDC_WAIT(); GDC_LAUNCH();
    int i4 = blockIdx.y * 128 + tid;
    const float4* G4 = (const float4*)g_G + (size_t)b*10240;
    float4*       M4 = (float4*)g_M       + (size_t)b*10240;
    float4 g[Tt];
    #pragma unroll
    for (int t = 0; t < Tt; ++t) g[t] = G4[t*1024 + i4];
    #pragma unroll
    for (int tp = 0; tp < Tt; ++tp) {
        float4 o = make_float4(0.f,0.f,0.f,0.f);
        #pragma unroll
        for (int t = 0; t < Tt; ++t) {
            float s = s_S[tp*Tt + t];
            FMA4(o, s, g[t]);
        }
        M4[tp*1024 + i4] = o;
    }
}

// ---------------- K3: layer. l=0: h1=relu(HW0+agg+b0), HW1=h1@W1^T --------------
//                        l=1: h2=relu(HW1+agg+b1) -> g_h2P + ctx
// dyn smem: l=0: s_B 4352 | s_At 4352 | s_W 4352 | s_Xt 4352 = 69632
//           l=1: s_B | s_At = 34816
__global__ __launch_bounds__(256) void k_layer(
    int l, const float* __restrict__ gnn_w, const float* __restrict__ gnn_b)
{
    const float* hw = (l == 0) ? g_xw0 : g_xw1;
    extern __shared__ __align__(16) float sm[];
    float* s_B  = sm;            // M'  [k][d] stride 68
    float* s_At = sm + 4352;     // nrm^T [k][r] stride 68
    float* s_W  = sm + 8704;     // W1^T [k][c] (l=0)
    float* s_Xt = sm + 13056;    // h1^T [k][r] (l=0)
    __shared__ __align__(16) float s_bias[64];
    __shared__ __align__(16) float s_csum[16][64];

    int t = blockIdx.x, b = blockIdx.y;
    int tid = threadIdx.x;
    int tx = tid & 15, ty = tid >> 4;

    if (tid < 64) s_bias[tid] = gnn_b[l*64 + tid];
    if (l == 0) {
        const float* Wp = gnn_w + 4096;     // W1
        #pragma unroll
        for (int it = 0; it < 16; ++it) {
            int e = tid + it*256;
            s_W[(e & 63)*68 + (e >> 6)] = Wp[e];   // W1^T [k][c]
        }
    }
    GDC_WAIT(); GDC_LAUNCH();
    int Kt = g_cnt[b*Tt + t];
    if (Kt == 0) return;
    int rbase = (b << 10) + g_off[b*Tt + t];

    const float4* Mp4 = (const float4*)&g_M[(b*Tt + t)*4096];
    #pragma unroll
    for (int it = 0; it < 4; ++it) {
        int e = tid + it*256;
        *(float4*)&s_B[(e >> 4)*68 + (e & 15)*4] = Mp4[e];   // natural [k][d]
    }
    float4 psum = make_float4(0.f,0.f,0.f,0.f);
    float4 bias = *(const float4*)&s_bias[tx*4];
    __syncthreads();

    for (int r0 = 0; r0 < Kt; r0 += 64) {
        // stage nrm^T tile (scalar, coalesced loads)
        #pragma unroll
        for (int it = 0; it < 16; ++it) {
            int e = tid + it*256;
            int rr = e >> 6, k = e & 63;
            int r = r0 + rr;
            s_At[k*68 + rr] = (r < Kt) ? g_nrmP[(rbase + r)*64 + k] : 0.f;
        }
        __syncthreads();

        // GEMM1: agg[r][d] = sum_k nrm[r][k] M'[k][d]
        float4 acc[4];
        #pragma unroll
        for (int i = 0; i < 4; ++i) acc[i] = make_float4(0.f,0.f,0.f,0.f);
        #pragma unroll 8
        for (int kk = 0; kk < 64; ++kk) {
            float4 a  = *(const float4*)&s_At[kk*68 + ty*4];
            float4 bb = *(const float4*)&s_B [kk*68 + tx*4];
            FMA4(acc[0], a.x, bb); FMA4(acc[1], a.y, bb);
            FMA4(acc[2], a.z, bb); FMA4(acc[3], a.w, bb);
        }

        if (l == 0) {
            // h1 = relu(HW0 + agg + b0), store transposed
            #pragma unroll
            for (int i = 0; i < 4; ++i) {
                int r = r0 + ty*4 + i;
                float4 x = acc[i];
                if (r < Kt) {
                    float4 hv = *(const float4*)&hw[(rbase + r)*64 + tx*4];
                    x.x = fmaxf(x.x + hv.x + bias.x, 0.f);
                    x.y = fmaxf(x.y + hv.y + bias.y, 0.f);
                    x.z = fmaxf(x.z + hv.z + bias.z, 0.f);
                    x.w = fmaxf(x.w + hv.w + bias.w, 0.f);
                } else {
                    x = make_float4(0.f,0.f,0.f,0.f);
                }
                s_Xt[(tx*4+0)*68 + ty*4 + i] = x.x;
                s_Xt[(tx*4+1)*68 + ty*4 + i] = x.y;
                s_Xt[(tx*4+2)*68 + ty*4 + i] = x.z;
                s_Xt[(tx*4+3)*68 + ty*4 + i] = x.w;
            }
            __syncthreads();

            // GEMM2: HW1[r][c] = sum_k h1[r][k] W1[c][k]
            float4 acc2[4];
            #pragma unroll
            for (int i = 0; i < 4; ++i) acc2[i] = make_float4(0.f,0.f,0.f,0.f);
            #pragma unroll 8
            for (int kk = 0; kk < 64; ++kk) {
                float4 a  = *(const float4*)&s_Xt[kk*68 + ty*4];
                float4 bb = *(const float4*)&s_W [kk*68 + tx*4];
                FMA4(acc2[0], a.x, bb); FMA4(acc2[1], a.y, bb);
                FMA4(acc2[2], a.z, bb); FMA4(acc2[3], a.w, bb);
            }
            #pragma unroll
            for (int i = 0; i < 4; ++i) {
                int r = r0 + ty*4 + i;
                if (r < Kt)
                    *(float4*)&g_xw1[(rbase + r)*64 + tx*4] = acc2[i];
            }
            __syncthreads();
        } else {
            // h2 = relu(HW1 + agg + b1)
            #pragma unroll
            for (int i = 0; i < 4; ++i) {
                int r = r0 + ty*4 + i;
                if (r < Kt) {
                    float4 x = acc[i];
                    float4 hv = *(const float4*)&hw[(rbase + r)*64 + tx*4];
                    x.x = fmaxf(x.x + hv.x + bias.x, 0.f);
                    x.y = fmaxf(x.y + hv.y + bias.y, 0.f);
                    x.z = fmaxf(x.z + hv.z + bias.z, 0.f);
                    x.w = fmaxf(x.w + hv.w + bias.w, 0.f);
                    *(float4*)&g_h2P[(rbase + r)*64 + tx*4] = x;
                    psum.x += x.x; psum.y += x.y; psum.z += x.z; psum.w += x.w;
                }
            }
            __syncthreads();
        }
    }

    if (l == 1) {
        *(float4*)&s_csum[ty][tx*4] = psum;
        __syncthreads();
        if (tid < 64) {
            float s = 0.f;
            #pragma unroll
            for (int q = 0; q < 16; ++q) s += s_csum[q][tid];
            atomicAdd(&g_ctx[b*64 + tid], s);
        }
    }
}

// ---------------- K4: head (+GRU per block, K=64, gathers h2P via pos) ----------
__global__ __launch_bounds__(256) void k_head(
    const float* __restrict__ prev, const float* __restrict__ wih,
    const float* __restrict__ whh,  const float* __restrict__ bih,
    const float* __restrict__ bhh,
    const float* __restrict__ w1, const float* __restrict__ b1,
    const float* __restrict__ w2, const float* __restrict__ b2,
    float* __restrict__ out)
{
    __shared__ __align__(16) float s_X[64*68];
    __shared__ __align__(16) float s_W[64*68];
    __shared__ __align__(16) float s_g[320];
    __shared__ __align__(16) float s_hs[64];
    __shared__ __align__(16) float s_w2[64];
    __shared__ int s_pos[64];
    int tid = threadIdx.x;
    int tx = tid & 15, ty = tid >> 4;
    int u = blockIdx.x;
    int base = u << 6;
    int b = u >> 4;

    #pragma unroll
    for (int it = 0; it < 16; ++it) {
        int e = tid + it*256;
        int j = e >> 6, k = e & 63;
        s_W[k*68 + j] = w1[j*96 + k];
    }
    if (tid < 64) s_w2[tid] = w2[tid];
    GDC_WAIT();
    if (tid < 64)       s_g[tid] = g_ctx[b*64 + tid] * (1.f/1024.f);
    else if (tid < 96)  s_g[tid] = prev[b*32 + (tid - 64)];
    else if (tid < 160) s_pos[tid - 96] = g_pos[base + (tid - 96)];
    __syncthreads();

    const float4* h24 = (const float4*)g_h2P;
    #pragma unroll
    for (int it = 0; it < 4; ++it) {
        int e = tid + it*256;
        int rr = e >> 4, kq = e & 15;
        *(float4*)&s_X[rr*68 + kq*4] = h24[s_pos[rr]*16 + kq];
    }
    if (tid < 96) {
        float gi = bih[tid], gh = bhh[tid];
        #pragma unroll 16
        for (int k = 0; k < 64; ++k) gi += s_g[k] * wih[tid*64 + k];
        #pragma unroll 16
        for (int k = 0; k < 32; ++k) gh += s_g[64 + k] * whh[tid*32 + k];
        s_g[96 + tid] = gi; s_g[192 + tid] = gh;
    }
    __syncthreads();
    if (tid < 32) {
        float r  = 1.f / (1.f + expf(-(s_g[96  + tid] + s_g[192 + tid])));
        float z  = 1.f / (1.f + expf(-(s_g[128 + tid] + s_g[224 + tid])));
        float nn = tanhf(s_g[160 + tid] + r * s_g[256 + tid]);
        float ns = (1.f - z)*nn + z*s_g[64 + tid];
        s_g[288 + tid] = ns;
        if ((u & 15) == 0) out[Bb*Nn + b*32 + tid] = ns;
    }
    __syncthreads();
    if (tid < 64) {
        float v = b1[tid];
        #pragma unroll
        for (int k = 0; k < 32; ++k) v += w1[tid*96 + 64 + k] * s_g[288 + k];
        s_hs[tid] = v;
    }
    __syncthreads();

    float4 hs = *(const float4*)&s_hs[tx*4];
    float4 acc[4] = {hs, hs, hs, hs};
    #pragma unroll 8
    for (int kk = 0; kk < 64; ++kk) {
        float4 bb = *(const float4*)&s_W[kk*68 + tx*4];
        float a0 = s_X[(ty*4+0)*68 + kk];
        float a1 = s_X[(ty*4+1)*68 + kk];
        float a2 = s_X[(ty*4+2)*68 + kk];
        float a3 = s_X[(ty*4+3)*68 + kk];
        FMA4(acc[0], a0, bb); FMA4(acc[1], a1, bb);
        FMA4(acc[2], a2, bb); FMA4(acc[3], a3, bb);
    }
    float4 w2v = *(const float4*)&s_w2[tx*4];
    float b2v = b2[0];
    #pragma unroll
    for (int i = 0; i < 4; ++i) {
        float y = fmaxf(acc[i].x, 0.f)*w2v.x + fmaxf(acc[i].y, 0.f)*w2v.y
                + fmaxf(acc[i].z, 0.f)*w2v.z + fmaxf(acc[i].w, 0.f)*w2v.w;
        #pragma unroll
        for (int o = 8; o > 0; o >>= 1) y += __shfl_xor_sync(0xffffffffu, y, o);
        if (tx == 0) out[base + ty*4 + i] = y + b2v;
    }
}

// ---------------- launch ---------------------------------------------------------
extern "C" void kernel_launch(void* const* d_in, const int* in_sizes, int n_in,
                              void* d_out, int out_size)
{
    const float* tf    = (const float*)d_in[0];
    const int*   types = (const int*)  d_in[1];
    const float* prev  = (const float*)d_in[2];
    const float* ew1   = (const float*)d_in[3];
    const float* eb1   = (const float*)d_in[4];
    const float* ew2   = (const float*)d_in[5];
    const float* eb2   = (const float*)d_in[6];
    const float* cont  = (const float*)d_in[7];
    const float* gw    = (const float*)d_in[8];
    const float* gb    = (const float*)d_in[9];
    const float* wih   = (const float*)d_in[10];
    const float* whh   = (const float*)d_in[11];
    const float* bih   = (const float*)d_in[12];
    const float* bhh   = (const float*)d_in[13];
    const float* hw1   = (const float*)d_in[14];
    const float* hb1   = (const float*)d_in[15];
    const float* hw2   = (const float*)d_in[16];
    const float* hb2   = (const float*)d_in[17];
    float* out = (float*)d_out;

    cudaFuncSetAttribute(k_layer, cudaFuncAttributeMaxDynamicSharedMemorySize, 69632);

    cudaLaunchAttribute at;
    at.id = cudaLaunchAttributeProgrammaticStreamSerialization;
    at.val.programmaticStreamSerializationAllowed = 1;
    cudaLaunchConfig_t cfg = {};
    cfg.attrs = &at;
    cfg.numAttrs = 1;
    cfg.stream = 0;

    k_bucket<<<Bb, 1024>>>(types);

    cfg.gridDim = dim3(1024); cfg.blockDim = dim3(256); cfg.dynamicSmemBytes = 0;
    cudaLaunchKernelEx(&cfg, k_enc, tf, ew1, eb1, ew2, eb2, gw);

    for (int l = 0; l < 2; ++l) {
        cfg.gridDim = dim3(Tt, Bb); cfg.blockDim = dim3(256); cfg.dynamicSmemBytes = 0;
        cudaLaunchKernelEx(&cfg, k_gmat, l);
        cfg.gridDim = dim3(Bb, 8); cfg.blockDim = dim3(128); cfg.dynamicSmemBytes = 0;
        cudaLaunchKernelEx(&cfg, k_combine, cont);
        cfg.gridDim = dim3(Tt, Bb); cfg.blockDim = dim3(256);
        cfg.dynamicSmemBytes = (l == 0) ? 69632 : 34816;
        cudaLaunchKernelEx(&cfg, k_layer, l, gw, gb);
    }
    cfg.gridDim = dim3(1024); cfg.blockDim = dim3(256); cfg.dynamicSmemBytes = 0;
    cudaLaunchKernelEx(&cfg, k_head, prev, wih, whh, bih, bhh,
                       hw1, hb1, hw2, hb2, out);
}